// round 6
// baseline (speedup 1.0000x reference)
#include <cuda_runtime.h>

#define T_STEPS 300
#define DIMX 40
#define HID 64
#define KDIM 104          // DIMX + HID
#define NGATE 256
#define BATCH 2048
#define ROWS 14
#define NBLK 147
#define OUTD 512

// LSTM smem (bytes): B[52][64][2] ulonglong2 = 106496 ; A double buffer 2*14*104*4
#define OFF_B   0
#define OFF_A0  106496
#define OFF_A1  112320
#define SMEM1   118144

// head smem: fs[8*64] + W1s[64*128] + y1s[8*128] + ls[8*512]
#define SMEM_H  ((8*64 + 64*128 + 8*128 + 8*512) * 4)

__device__ float g_final[BATCH * HID];
__device__ float g_c[BATCH * HID];
__device__ float g_h[BATCH * HID];

__device__ __forceinline__ float fast_rcp(float x) {
    float y; asm("rcp.approx.f32 %0, %1;" : "=f"(y) : "f"(x)); return y;
}
__device__ __forceinline__ float tanh_fast(float x) {
    float y; asm("tanh.approx.f32 %0, %1;" : "=f"(y) : "f"(x)); return y;
}
__device__ __forceinline__ unsigned long long pack2(float a, float b) {
    unsigned long long r;
    asm("mov.b64 %0, {%1, %2};" : "=l"(r) : "f"(a), "f"(b));
    return r;
}
__device__ __forceinline__ float2 unpack2(unsigned long long v) {
    float2 r;
    asm("mov.b64 {%0, %1}, %2;" : "=f"(r.x), "=f"(r.y) : "l"(v));
    return r;
}
#define FMA2(d, a, b) asm("fma.rn.f32x2 %0, %1, %2, %0;" : "+l"(d) : "l"(a), "l"(b))

// ---------------------------------------------------------------------------
// Persistent LSTM, gate-split: 256 threads = 2 row-groups(7) x 64 h x 2 gp.
// tid = grp*128 + h*2 + gp. Thread (h, gp) computes gate cols {i,j} (gp=0)
// or {f,o} (gp=1) of unit h for its 7 rows. Activated gates are exchanged
// with the lane-adjacent partner via shfl_xor(1); both threads compute the
// (identical) cell update; gp=0 writes h. 2 warps/SMSP hides LDS/MUFU latency
// (R4 had 1 warp/SMSP: issue=27.5%, step latency-exposed 7200cyc vs 2912 FMA).
// B layout (ulonglong2): Bs2[kp*128 + h*2 + gp] = {kpair(gate 2gp), kpair(gate 2gp+1)}
//   where kpair(g) = {W[2kp][g*64+h], W[2kp+1][g*64+h]}.
// Thread load addr = kp*2048 + h*32 + gp*16 -> warp spans 512B contiguous, conflict-free.
// A double-buffered; one __syncthreads per step.
// ---------------------------------------------------------------------------
__global__ __launch_bounds__(256, 1) void lstm_kernel(
    const float* __restrict__ X,      // [B][T][40]
    const int*   __restrict__ seq,    // [B]
    const float* __restrict__ Wk,     // [104][256]
    const float* __restrict__ bias,   // [256]
    int t0, int t1)
{
    extern __shared__ char smem[];
    unsigned long long* Bs = (unsigned long long*)(smem + OFF_B);
    float* Abuf[2] = { (float*)(smem + OFF_A0), (float*)(smem + OFF_A1) };

    const int tid = threadIdx.x;
    const int g0  = blockIdx.x * ROWS;
    const int gp  = tid & 1;
    const int h   = (tid >> 1) & 63;
    const int grp = tid >> 7;
    const int rbase = grp * 7;

    // ---- build B ----
    for (int i = tid; i < 52 * 256; i += 256) {
        int kp  = i >> 8;
        int rem = i & 255;                 // h*4 + gpi*2 + s
        int hh  = rem >> 2;
        int gpi = (rem >> 1) & 1;
        int s   = rem & 1;
        int col = (2 * gpi + s) * 64 + hh;
        Bs[i] = pack2(__ldg(Wk + (2 * kp) * NGATE + col),
                      __ldg(Wk + (2 * kp + 1) * NGATE + col));
    }
    // ---- zero h region of both buffers ----
    for (int i = tid; i < ROWS * HID; i += 256) {
        int r = i / HID, hh = i % HID;
        Abuf[0][r * KDIM + DIMX + hh] = 0.0f;
        Abuf[1][r * KDIM + DIMX + hh] = 0.0f;
    }

    // ---- x streaming: 560 elems/step, 3 slots per thread ----
    const float* xp[3];
    bool vld[3];
    int  sloc[3];
    #pragma unroll
    for (int s = 0; s < 3; s++) {
        int e = tid + 256 * s;
        bool inr = e < ROWS * DIMX;
        int r = inr ? e / DIMX : 0;
        vld[s]  = inr && ((g0 + r) < BATCH);
        sloc[s] = inr ? (r * KDIM + e % DIMX) : 0;
        xp[s]   = X + (size_t)(g0 + (vld[s] ? r : 0)) * (T_STEPS * DIMX) + (e % DIMX);
    }
    // x_{t0} into buffer 0
    #pragma unroll
    for (int s = 0; s < 3; s++) {
        if (tid + 256 * s < ROWS * DIMX)
            Abuf[0][sloc[s]] = vld[s] ? __ldg(xp[s] + t0 * DIMX) : 0.0f;
    }

    // ---- per-thread bias / activation constants ----
    // gp=0: gates (i, j);  gp=1: gates (f+1, o)
    const float b0r = gp ? (__ldg(bias + 128 + h) + 1.0f) : __ldg(bias + h);
    const float b1r = gp ? __ldg(bias + 192 + h) : __ldg(bias + 64 + h);
    const float s1  = gp ? 0.5f : 1.0f;   // a1 = tanh(v1*s1)*s1 + h1
    const float h1  = gp ? 0.5f : 0.0f;

    // ---- per-row state ----
    float creg[7];
    int   idxr[7];
    #pragma unroll
    for (int r = 0; r < 7; r++) {
        int row = g0 + rbase + r;
        bool ok = row < BATCH;
        idxr[r] = ok ? (__ldg(seq + row) - 1) : -2;
        if (t0 == 0) {
            creg[r] = 0.0f;
        } else {
            creg[r] = ok ? g_c[(size_t)row * HID + h] : 0.0f;
            if (gp == 0)
                Abuf[0][(rbase + r) * KDIM + DIMX + h] = ok ? g_h[(size_t)row * HID + h] : 0.0f;
        }
    }
    float* finalp = g_final + (size_t)(g0 + rbase) * HID + h;

    const ulonglong2* Bh = ((const ulonglong2*)Bs) + h * 2 + gp;

    __syncthreads();

    int p = 0;
    for (int t = t0; t < t1; t++) {
        float* Ap = Abuf[p];
        float* Aq = Abuf[1 - p];

        // prefetch x_{t+1}
        float xr[3];
        const bool pf = (t + 1 < T_STEPS);
        if (pf) {
            const int off = (t + 1) * DIMX;
            #pragma unroll
            for (int s = 0; s < 3; s++) xr[s] = vld[s] ? __ldg(xp[s] + off) : 0.0f;
        }

        // ---- GEMM: 7 rows x 2 gate-cols, k packed in f32x2 ----
        unsigned long long acc[7][2];
        #pragma unroll
        for (int r = 0; r < 7; r++) { acc[r][0] = 0ULL; acc[r][1] = 0ULL; }
        const ulonglong2* Ap2 = (const ulonglong2*)(Ap + rbase * KDIM);

        #pragma unroll 2
        for (int kp2 = 0; kp2 < 26; kp2++) {        // 4 k per iter
            ulonglong2 b0 = Bh[(2 * kp2)     * 128];  // {gate 2gp, gate 2gp+1} @ kp
            ulonglong2 b1 = Bh[(2 * kp2 + 1) * 128];
            #pragma unroll
            for (int r = 0; r < 7; r++) {
                ulonglong2 a = Ap2[r * 26 + kp2];   // {k0,k1},{k2,k3}
                FMA2(acc[r][0], a.x, b0.x);
                FMA2(acc[r][1], a.x, b0.y);
                FMA2(acc[r][0], a.y, b1.x);
                FMA2(acc[r][1], a.y, b1.y);
            }
        }

        // ---- stage x_{t+1} into next buffer ----
        if (pf) {
            #pragma unroll
            for (int s = 0; s < 3; s++) {
                if (tid + 256 * s < ROWS * DIMX) Aq[sloc[s]] = xr[s];
            }
        }

        // ---- epilogue: activations, gate exchange via shfl, cell update ----
        #pragma unroll
        for (int r = 0; r < 7; r++) {
            float2 z0 = unpack2(acc[r][0]);
            float2 z1 = unpack2(acc[r][1]);
            float v0 = z0.x + z0.y + b0r;          // i or f(+1)
            float v1 = z1.x + z1.y + b1r;          // j or o
            float a0 = 0.5f * tanh_fast(0.5f * v0) + 0.5f;       // ig or fg
            float a1 = tanh_fast(v1 * s1) * s1 + h1;             // jg or og
            float o0 = __shfl_xor_sync(0xffffffffu, a0, 1);
            float o1 = __shfl_xor_sync(0xffffffffu, a1, 1);
            float ig = gp ? o0 : a0;
            float jg = gp ? o1 : a1;
            float fg = gp ? a0 : o0;
            float og = gp ? a1 : o1;
            float c  = creg[r] * fg + ig * jg;
            creg[r] = c;
            float hn = tanh_fast(c) * og;
            if (gp == 0) {
                Aq[(rbase + r) * KDIM + DIMX + h] = hn;
                if (t == idxr[r]) finalp[r * HID] = hn;
            }
        }

        __syncthreads();
        p ^= 1;
    }

    // ---- save carry state if more steps remain ----
    if (t1 < T_STEPS && gp == 0) {
        #pragma unroll
        for (int r = 0; r < 7; r++) {
            int row = g0 + rbase + r;
            if (row < BATCH) {
                g_c[(size_t)row * HID + h] = creg[r];
                g_h[(size_t)row * HID + h] = Abuf[p][(rbase + r) * KDIM + DIMX + h];
            }
        }
    }
}

// ---------------------------------------------------------------------------
// Head: 256 blocks x 256 threads, 8 batch rows per block.
// ---------------------------------------------------------------------------
__global__ __launch_bounds__(256, 1) void head_kernel(
    const float* __restrict__ W1, const float* __restrict__ b1,
    const float* __restrict__ gamma, const float* __restrict__ beta,
    const float* __restrict__ mean, const float* __restrict__ var,
    const float* __restrict__ W2, const float* __restrict__ b2,
    float* __restrict__ out)
{
    extern __shared__ char smem[];
    float* fs  = (float*)smem;            // [8][64]
    float* W1s = fs + 8 * 64;             // [64][128]
    float* y1s = W1s + 64 * 128;          // [8][128]
    float* ls  = y1s + 8 * 128;           // [8][512]

    const int tid = threadIdx.x;
    const int g0  = blockIdx.x * 8;

    for (int i = tid; i < 8 * 64 / 4; i += 256)
        ((float4*)fs)[i] = ((const float4*)g_final)[g0 * 16 + i];
    for (int i = tid; i < 64 * 128 / 4; i += 256)
        ((float4*)W1s)[i] = ((const float4*)W1)[i];
    __syncthreads();

    // dense1 + relu + BN
    {
        const int c  = tid & 127;
        const int r0 = (tid >> 7) * 4;
        const float scale = gamma[c] * rsqrtf(var[c] + 1e-3f);
        const float shift = beta[c] - mean[c] * scale;
        const float bb = b1[c];
        #pragma unroll
        for (int r = r0; r < r0 + 4; r++) {
            float acc = bb;
            #pragma unroll 8
            for (int k = 0; k < 64; k++) acc += fs[r * 64 + k] * W1s[k * 128 + c];
            acc = fmaxf(acc, 0.0f);
            y1s[r * 128 + c] = acc * scale + shift;
        }
    }
    __syncthreads();

    // dense2: cols {2*tid, 2*tid+1}, k-packed f32x2
    {
        const int c0 = 2 * tid;
        unsigned long long acc[8][2];
        #pragma unroll
        for (int r = 0; r < 8; r++) { acc[r][0] = 0ULL; acc[r][1] = 0ULL; }

        #pragma unroll 4
        for (int kp2 = 0; kp2 < 32; kp2++) {
            const int k = 4 * kp2;
            float2 w0 = *(const float2*)(W2 + (size_t)(k    ) * OUTD + c0);
            float2 w1 = *(const float2*)(W2 + (size_t)(k + 1) * OUTD + c0);
            float2 w2 = *(const float2*)(W2 + (size_t)(k + 2) * OUTD + c0);
            float2 w3 = *(const float2*)(W2 + (size_t)(k + 3) * OUTD + c0);
            unsigned long long p01a = pack2(w0.x, w1.x);
            unsigned long long p23a = pack2(w2.x, w3.x);
            unsigned long long p01b = pack2(w0.y, w1.y);
            unsigned long long p23b = pack2(w2.y, w3.y);
            #pragma unroll
            for (int r = 0; r < 8; r++) {
                ulonglong2 y = *(const ulonglong2*)(y1s + r * 128 + k);
                FMA2(acc[r][0], y.x, p01a);
                FMA2(acc[r][0], y.y, p23a);
                FMA2(acc[r][1], y.x, p01b);
                FMA2(acc[r][1], y.y, p23b);
            }
        }
        const float bb0 = b2[c0], bb1 = b2[c0 + 1];
        #pragma unroll
        for (int r = 0; r < 8; r++) {
            float2 pa = unpack2(acc[r][0]);
            float2 pb = unpack2(acc[r][1]);
            ls[r * OUTD + c0]     = pa.x + pa.y + bb0;
            ls[r * OUTD + c0 + 1] = pb.x + pb.y + bb1;
        }
    }
    __syncthreads();

    // softmax: 8 warps, one row each
    {
        const int w = tid >> 5, lane = tid & 31;
        float v[16];
        float m = -1e30f;
        #pragma unroll
        for (int j = 0; j < 16; j++) {
            v[j] = ls[w * OUTD + lane + 32 * j];
            m = fmaxf(m, v[j]);
        }
        #pragma unroll
        for (int s = 16; s; s >>= 1) m = fmaxf(m, __shfl_xor_sync(0xffffffffu, m, s));
        float sum = 0.0f;
        #pragma unroll
        for (int j = 0; j < 16; j++) { v[j] = __expf(v[j] - m); sum += v[j]; }
        #pragma unroll
        for (int s = 16; s; s >>= 1) sum += __shfl_xor_sync(0xffffffffu, sum, s);
        const float inv = fast_rcp(sum);
        float* orow = out + (size_t)(g0 + w) * OUTD + lane;
        #pragma unroll
        for (int j = 0; j < 16; j++) orow[32 * j] = v[j] * inv;
    }
}

extern "C" void kernel_launch(void* const* d_in, const int* in_sizes, int n_in,
                              void* d_out, int out_size) {
    const float* X     = (const float*)d_in[0];
    const int*   seq   = (const int*)  d_in[1];
    const float* Wk    = (const float*)d_in[2];
    const float* bias  = (const float*)d_in[3];
    const float* W1    = (const float*)d_in[4];
    const float* b1    = (const float*)d_in[5];
    const float* gamma = (const float*)d_in[6];
    const float* beta  = (const float*)d_in[7];
    const float* mean  = (const float*)d_in[8];
    const float* var   = (const float*)d_in[9];
    const float* W2    = (const float*)d_in[10];
    const float* b2    = (const float*)d_in[11];
    float* out = (float*)d_out;

    cudaFuncSetAttribute(lstm_kernel, cudaFuncAttributeMaxDynamicSharedMemorySize, SMEM1);
    cudaFuncSetAttribute(head_kernel, cudaFuncAttributeMaxDynamicSharedMemorySize, SMEM_H);

    lstm_kernel<<<NBLK, 256, SMEM1>>>(X, seq, Wk, bias, 0, 150);
    lstm_kernel<<<NBLK, 256, SMEM1>>>(X, seq, Wk, bias, 150, 300);
    head_kernel<<<BATCH / 8, 256, SMEM_H>>>(W1, b1, gamma, beta, mean, var, W2, b2, out);
}

// round 9
// speedup vs baseline: 1.1259x; 1.1259x over previous
#include <cuda_runtime.h>

#define T_STEPS 300
#define DIMX 40
#define HID 64
#define KDIM 104          // DIMX + HID
#define NGATE 256
#define BATCH 2048
#define ROWS 14
#define NBLK 147
#define OUTD 512

// LSTM smem (bytes): B[52][256] u64 = 106496 ; A double buffer 2*14*104*4
#define OFF_B   0
#define OFF_A0  106496
#define OFF_A1  112320
#define SMEM1   118144

// head smem: fs[8*64] + W1s[64*128] + y1s[8*128] + ls[8*512]
#define SMEM_H  ((8*64 + 64*128 + 8*128 + 8*512) * 4)

__device__ float g_final[BATCH * HID];
__device__ float g_c[BATCH * HID];
__device__ float g_h[BATCH * HID];

__device__ __forceinline__ float fast_rcp(float x) {
    float y; asm("rcp.approx.f32 %0, %1;" : "=f"(y) : "f"(x)); return y;
}
__device__ __forceinline__ float tanh_fast(float x) {
    float y; asm("tanh.approx.f32 %0, %1;" : "=f"(y) : "f"(x)); return y;
}
__device__ __forceinline__ unsigned long long pack2(float a, float b) {
    unsigned long long r;
    asm("mov.b64 %0, {%1, %2};" : "=l"(r) : "f"(a), "f"(b));
    return r;
}
__device__ __forceinline__ float2 unpack2(unsigned long long v) {
    float2 r;
    asm("mov.b64 {%0, %1}, %2;" : "=f"(r.x), "=f"(r.y) : "l"(v));
    return r;
}
#define FMA2(d, a, b) asm("fma.rn.f32x2 %0, %1, %2, %0;" : "+l"(d) : "l"(a), "l"(b))

// ---------------------------------------------------------------------------
// Persistent LSTM, intra-warp K-split:
//   256 threads = 2 row-groups(7 rows) x 4 h-groups x 32 lanes.
//   lane = kw*16 + q;  kw = k-half (k in [kw*52, kw*52+52)), h = wcg*16 + q.
//   Each thread: all 4 gates of unit h, 7 rows, over its 52-k half.
//   Partial sums merged with one shfl_xor(16) per output (28/thread), then
//   the full cell update runs locally in both halves (identical results);
//   kw=0 writes h.
// Memory economy per warp per step: 52 B-LDS.128 (both kw halves packed per
//   instruction, 512B payload) + 91 A-LDS.128 (dual 16B broadcast, 1 wf)
//   = 143 instr/warp, 1144/SM  == R4's best economy, now at 2 warps/SMSP.
// B layout (u64): idx = kp*256 + j*128 + 2h + s, value = k-pair of gate 2j+s.
// A double-buffered; one __syncthreads per step.
// ---------------------------------------------------------------------------
__global__ __launch_bounds__(256, 1) void lstm_kernel(
    const float* __restrict__ X,      // [B][T][40]
    const int*   __restrict__ seq,    // [B]
    const float* __restrict__ Wk,     // [104][256]
    const float* __restrict__ bias,   // [256]
    int t0, int t1)
{
    extern __shared__ char smem[];
    unsigned long long* Bs = (unsigned long long*)(smem + OFF_B);
    float* Abuf[2] = { (float*)(smem + OFF_A0), (float*)(smem + OFF_A1) };

    const int tid  = threadIdx.x;
    const int g0   = blockIdx.x * ROWS;
    const int lane = tid & 31;
    const int w    = tid >> 5;
    const int grp  = w >> 2;            // row group 0/1
    const int wcg  = w & 3;             // h group 0..3
    const int kw   = lane >> 4;         // k half 0/1
    const int q    = lane & 15;
    const int h    = wcg * 16 + q;      // hidden unit 0..63
    const int rbase = grp * 7;

    // ---- build B: Bs[kp*256 + j*128 + 2h + s] = kpair(gate 2j+s, h) ----
    for (int i = tid; i < 52 * 256; i += 256) {
        int kp  = i >> 8;
        int rem = i & 255;
        int j   = rem >> 7;
        int hh  = (rem >> 1) & 63;
        int s   = rem & 1;
        int col = (2 * j + s) * 64 + hh;
        Bs[i] = pack2(__ldg(Wk + (2 * kp) * NGATE + col),
                      __ldg(Wk + (2 * kp + 1) * NGATE + col));
    }
    // ---- zero h region of both buffers ----
    for (int i = tid; i < ROWS * HID; i += 256) {
        int r = i / HID, hh = i % HID;
        Abuf[0][r * KDIM + DIMX + hh] = 0.0f;
        Abuf[1][r * KDIM + DIMX + hh] = 0.0f;
    }

    // ---- x streaming: 560 elems/step, 3 slots per thread ----
    const float* xp[3];
    bool vld[3];
    int  sloc[3];
    #pragma unroll
    for (int s = 0; s < 3; s++) {
        int e = tid + 256 * s;
        bool inr = e < ROWS * DIMX;
        int r = inr ? e / DIMX : 0;
        vld[s]  = inr && ((g0 + r) < BATCH);
        sloc[s] = inr ? (r * KDIM + e % DIMX) : 0;
        xp[s]   = X + (size_t)(g0 + (vld[s] ? r : 0)) * (T_STEPS * DIMX) + (e % DIMX);
    }
    #pragma unroll
    for (int s = 0; s < 3; s++) {
        if (tid + 256 * s < ROWS * DIMX)
            Abuf[0][sloc[s]] = vld[s] ? __ldg(xp[s] + t0 * DIMX) : 0.0f;
    }

    // ---- bias (forget bias folded) ----
    const float bi = __ldg(bias + h);
    const float bj = __ldg(bias + 64 + h);
    const float bf = __ldg(bias + 128 + h) + 1.0f;
    const float bo = __ldg(bias + 192 + h);

    // ---- per-row state ----
    float creg[7];
    int   idxr[7];
    #pragma unroll
    for (int r = 0; r < 7; r++) {
        int row = g0 + rbase + r;
        bool ok = row < BATCH;
        idxr[r] = ok ? (__ldg(seq + row) - 1) : -2;
        if (t0 == 0) {
            creg[r] = 0.0f;
        } else {
            creg[r] = ok ? g_c[(size_t)row * HID + h] : 0.0f;
            if (kw == 0)
                Abuf[0][(rbase + r) * KDIM + DIMX + h] = ok ? g_h[(size_t)row * HID + h] : 0.0f;
        }
    }
    float* finalp = g_final + (size_t)(g0 + rbase) * HID + h;

    const ulonglong2* B2 = (const ulonglong2*)Bs;   // index kp*128 + j*64 + h
    const int kpb = kw * 26;

    __syncthreads();

    int p = 0;
    for (int t = t0; t < t1; t++) {
        float* Ap = Abuf[p];
        float* Aq = Abuf[1 - p];

        // prefetch x_{t+1}
        float xr[3];
        const bool pf = (t + 1 < T_STEPS);
        if (pf) {
            const int off = (t + 1) * DIMX;
            #pragma unroll
            for (int s = 0; s < 3; s++) xr[s] = vld[s] ? __ldg(xp[s] + off) : 0.0f;
        }

        // ---- GEMM: 7 rows x 4 gates over this thread's 52-k half ----
        unsigned long long acc[7][4];
        #pragma unroll
        for (int r = 0; r < 7; r++) {
            acc[r][0] = 0ULL; acc[r][1] = 0ULL; acc[r][2] = 0ULL; acc[r][3] = 0ULL;
        }
        const float* Arow = Ap + rbase * KDIM + kw * 52;

        #pragma unroll
        for (int it = 0; it < 13; it++) {           // 4 k per iter
            ulonglong2 b00 = B2[(kpb + 2 * it)     * 128 + h];       // {i,j} @ kp0
            ulonglong2 b01 = B2[(kpb + 2 * it)     * 128 + 64 + h];  // {f,o} @ kp0
            ulonglong2 b10 = B2[(kpb + 2 * it + 1) * 128 + h];       // {i,j} @ kp1
            ulonglong2 b11 = B2[(kpb + 2 * it + 1) * 128 + 64 + h];  // {f,o} @ kp1
            #pragma unroll
            for (int r = 0; r < 7; r++) {
                ulonglong2 a = *(const ulonglong2*)(Arow + r * KDIM + it * 4);
                FMA2(acc[r][0], a.x, b00.x);
                FMA2(acc[r][1], a.x, b00.y);
                FMA2(acc[r][2], a.x, b01.x);
                FMA2(acc[r][3], a.x, b01.y);
                FMA2(acc[r][0], a.y, b10.x);
                FMA2(acc[r][1], a.y, b10.y);
                FMA2(acc[r][2], a.y, b11.x);
                FMA2(acc[r][3], a.y, b11.y);
            }
        }

        // ---- stage x_{t+1} into next buffer ----
        if (pf) {
            #pragma unroll
            for (int s = 0; s < 3; s++) {
                if (tid + 256 * s < ROWS * DIMX) Aq[sloc[s]] = xr[s];
            }
        }

        // ---- epilogue: k-half reduction (shfl 16), gates, cell update ----
        #pragma unroll
        for (int r = 0; r < 7; r++) {
            float2 pi = unpack2(acc[r][0]);
            float2 pj = unpack2(acc[r][1]);
            float2 pf2 = unpack2(acc[r][2]);
            float2 po = unpack2(acc[r][3]);
            float si = pi.x + pi.y;
            float sj = pj.x + pj.y;
            float sf = pf2.x + pf2.y;
            float so = po.x + po.y;
            si += __shfl_xor_sync(0xffffffffu, si, 16);
            sj += __shfl_xor_sync(0xffffffffu, sj, 16);
            sf += __shfl_xor_sync(0xffffffffu, sf, 16);
            so += __shfl_xor_sync(0xffffffffu, so, 16);
            float ig = 0.5f * tanh_fast(0.5f * (si + bi)) + 0.5f;
            float jg = tanh_fast(sj + bj);
            float fg = 0.5f * tanh_fast(0.5f * (sf + bf)) + 0.5f;
            float og = 0.5f * tanh_fast(0.5f * (so + bo)) + 0.5f;
            float c  = creg[r] * fg + ig * jg;
            creg[r] = c;
            float hn = tanh_fast(c) * og;
            if (kw == 0) {
                Aq[(rbase + r) * KDIM + DIMX + h] = hn;
                if (t == idxr[r]) finalp[r * HID] = hn;
            }
        }

        __syncthreads();
        p ^= 1;
    }

    // ---- save carry state if more steps remain ----
    if (t1 < T_STEPS && kw == 0) {
        #pragma unroll
        for (int r = 0; r < 7; r++) {
            int row = g0 + rbase + r;
            if (row < BATCH) {
                g_c[(size_t)row * HID + h] = creg[r];
                g_h[(size_t)row * HID + h] = Abuf[p][(rbase + r) * KDIM + DIMX + h];
            }
        }
    }
}

// ---------------------------------------------------------------------------
// Head: 256 blocks x 256 threads, 8 batch rows per block.
// ---------------------------------------------------------------------------
__global__ __launch_bounds__(256, 1) void head_kernel(
    const float* __restrict__ W1, const float* __restrict__ b1,
    const float* __restrict__ gamma, const float* __restrict__ beta,
    const float* __restrict__ mean, const float* __restrict__ var,
    const float* __restrict__ W2, const float* __restrict__ b2,
    float* __restrict__ out)
{
    extern __shared__ char smem[];
    float* fs  = (float*)smem;            // [8][64]
    float* W1s = fs + 8 * 64;             // [64][128]
    float* y1s = W1s + 64 * 128;          // [8][128]
    float* ls  = y1s + 8 * 128;           // [8][512]

    const int tid = threadIdx.x;
    const int g0  = blockIdx.x * 8;

    for (int i = tid; i < 8 * 64 / 4; i += 256)
        ((float4*)fs)[i] = ((const float4*)g_final)[g0 * 16 + i];
    for (int i = tid; i < 64 * 128 / 4; i += 256)
        ((float4*)W1s)[i] = ((const float4*)W1)[i];
    __syncthreads();

    // dense1 + relu + BN
    {
        const int c  = tid & 127;
        const int r0 = (tid >> 7) * 4;
        const float scale = gamma[c] * rsqrtf(var[c] + 1e-3f);
        const float shift = beta[c] - mean[c] * scale;
        const float bb = b1[c];
        #pragma unroll
        for (int r = r0; r < r0 + 4; r++) {
            float acc = bb;
            #pragma unroll 8
            for (int k = 0; k < 64; k++) acc += fs[r * 64 + k] * W1s[k * 128 + c];
            acc = fmaxf(acc, 0.0f);
            y1s[r * 128 + c] = acc * scale + shift;
        }
    }
    __syncthreads();

    // dense2: cols {2*tid, 2*tid+1}, k-packed f32x2
    {
        const int c0 = 2 * tid;
        unsigned long long acc[8][2];
        #pragma unroll
        for (int r = 0; r < 8; r++) { acc[r][0] = 0ULL; acc[r][1] = 0ULL; }

        #pragma unroll 4
        for (int kp2 = 0; kp2 < 32; kp2++) {
            const int k = 4 * kp2;
            float2 w0 = *(const float2*)(W2 + (size_t)(k    ) * OUTD + c0);
            float2 w1 = *(const float2*)(W2 + (size_t)(k + 1) * OUTD + c0);
            float2 w2 = *(const float2*)(W2 + (size_t)(k + 2) * OUTD + c0);
            float2 w3 = *(const float2*)(W2 + (size_t)(k + 3) * OUTD + c0);
            unsigned long long p01a = pack2(w0.x, w1.x);
            unsigned long long p23a = pack2(w2.x, w3.x);
            unsigned long long p01b = pack2(w0.y, w1.y);
            unsigned long long p23b = pack2(w2.y, w3.y);
            #pragma unroll
            for (int r = 0; r < 8; r++) {
                ulonglong2 y = *(const ulonglong2*)(y1s + r * 128 + k);
                FMA2(acc[r][0], y.x, p01a);
                FMA2(acc[r][0], y.y, p23a);
                FMA2(acc[r][1], y.x, p01b);
                FMA2(acc[r][1], y.y, p23b);
            }
        }
        const float bb0 = b2[c0], bb1 = b2[c0 + 1];
        #pragma unroll
        for (int r = 0; r < 8; r++) {
            float2 pa = unpack2(acc[r][0]);
            float2 pb = unpack2(acc[r][1]);
            ls[r * OUTD + c0]     = pa.x + pa.y + bb0;
            ls[r * OUTD + c0 + 1] = pb.x + pb.y + bb1;
        }
    }
    __syncthreads();

    // softmax: 8 warps, one row each
    {
        const int w = tid >> 5, lane = tid & 31;
        float v[16];
        float m = -1e30f;
        #pragma unroll
        for (int j = 0; j < 16; j++) {
            v[j] = ls[w * OUTD + lane + 32 * j];
            m = fmaxf(m, v[j]);
        }
        #pragma unroll
        for (int s = 16; s; s >>= 1) m = fmaxf(m, __shfl_xor_sync(0xffffffffu, m, s));
        float sum = 0.0f;
        #pragma unroll
        for (int j = 0; j < 16; j++) { v[j] = __expf(v[j] - m); sum += v[j]; }
        #pragma unroll
        for (int s = 16; s; s >>= 1) sum += __shfl_xor_sync(0xffffffffu, sum, s);
        const float inv = fast_rcp(sum);
        float* orow = out + (size_t)(g0 + w) * OUTD + lane;
        #pragma unroll
        for (int j = 0; j < 16; j++) orow[32 * j] = v[j] * inv;
    }
}

extern "C" void kernel_launch(void* const* d_in, const int* in_sizes, int n_in,
                              void* d_out, int out_size) {
    const float* X     = (const float*)d_in[0];
    const int*   seq   = (const int*)  d_in[1];
    const float* Wk    = (const float*)d_in[2];
    const float* bias  = (const float*)d_in[3];
    const float* W1    = (const float*)d_in[4];
    const float* b1    = (const float*)d_in[5];
    const float* gamma = (const float*)d_in[6];
    const float* beta  = (const float*)d_in[7];
    const float* mean  = (const float*)d_in[8];
    const float* var   = (const float*)d_in[9];
    const float* W2    = (const float*)d_in[10];
    const float* b2    = (const float*)d_in[11];
    float* out = (float*)d_out;

    cudaFuncSetAttribute(lstm_kernel, cudaFuncAttributeMaxDynamicSharedMemorySize, SMEM1);
    cudaFuncSetAttribute(head_kernel, cudaFuncAttributeMaxDynamicSharedMemorySize, SMEM_H);

    lstm_kernel<<<NBLK, 256, SMEM1>>>(X, seq, Wk, bias, 0, 150);
    lstm_kernel<<<NBLK, 256, SMEM1>>>(X, seq, Wk, bias, 150, 300);
    head_kernel<<<BATCH / 8, 256, SMEM_H>>>(W1, b1, gamma, beta, mean, var, W2, b2, out);
}